// round 17
// baseline (speedup 1.0000x reference)
#include <cuda_runtime.h>
#include <cuda_fp16.h>
#include <cstdint>

#define N_NODES 10000
#define WPR     313              // ceil(10000/32)
#define D       256
#define E_EDGES 320000
#define MAXDEG  1024             // >> max row degree (~110 for this graph)

// Scratch (no allocs allowed)
__device__ uint32_t g_bits[N_NODES * WPR];   // 12.52 MB bitmask (multiple of 16B)
__device__ int      g_deg[N_NODES];          // unique-neighbor counts (popcount)
__device__ __half2  g_hh[N_NODES * (D / 2)]; // h = x@W (UNSCALED fp16)
__device__ __half   g_wt[D * D];             // W^T in fp16 (n-major, k contiguous)
__device__ int      g_odd = 0;               // OR-only => deterministic across replays

// ---------------------------------------------------------------------------
// Clear the bitmask (single launch, uint4 stores).
__global__ void clear_kernel() {
    int i = blockIdx.x * blockDim.x + threadIdx.x;
    if (i < N_NODES * WPR / 4)
        ((uint4*)g_bits)[i] = make_uint4(0u, 0u, 0u, 0u);
}

// ---------------------------------------------------------------------------
// Detect edge_index dtype (int64 => odd 32-bit words of values <10000 are 0),
// sampled over the first 65536 pairs. Also W->W^T fp16.
__global__ void detect_kernel(const int* __restrict__ ei, const float* __restrict__ w) {
    int gid = blockIdx.x * blockDim.x + threadIdx.x;
    if (gid < D * D) {
        int k = gid >> 8, n = gid & 255;
        g_wt[n * D + k] = __float2half(w[gid]);   // coalesced read, 2B scatter (128KB)
    }
    unsigned v = (unsigned)ei[2 * gid + 1];       // 65536 odd words sampled
    #pragma unroll
    for (int o = 16; o; o >>= 1) v |= __shfl_xor_sync(0xffffffffu, v, o);
    if ((threadIdx.x & 31) == 0 && v) atomicOr(&g_odd, 1);
}

// ---------------------------------------------------------------------------
// Set adjacency bits (symmetric, OR dedup, RED fire-and-forget).
// 4 edges/thread with vectorized loads -> MLP 8 on the RED stream.
__global__ void set_bits_kernel(const int* __restrict__ ei32) {
    int e0 = (blockIdx.x * blockDim.x + threadIdx.x) * 4;
    if (e0 >= E_EDGES) return;
    unsigned src[4], dst[4];
    if (g_odd == 0) {  // int64 layout: 4 values = 2 uint4 (take low words)
        const uint4* s64 = (const uint4*)(ei32 + 2 * e0);
        uint4 a = s64[0], b = s64[1];
        src[0] = a.x; src[1] = a.z; src[2] = b.x; src[3] = b.z;
        const uint4* d64 = (const uint4*)(ei32 + 2 * E_EDGES + 2 * e0);
        uint4 c = d64[0], d = d64[1];
        dst[0] = c.x; dst[1] = c.z; dst[2] = d.x; dst[3] = d.z;
    } else {           // int32 layout: 4 values = 1 uint4
        uint4 a = *(const uint4*)(ei32 + e0);
        uint4 b = *(const uint4*)(ei32 + E_EDGES + e0);
        src[0] = a.x; src[1] = a.y; src[2] = a.z; src[3] = a.w;
        dst[0] = b.x; dst[1] = b.y; dst[2] = b.z; dst[3] = b.w;
    }
    #pragma unroll
    for (int i = 0; i < 4; i++) {
        atomicOr(&g_bits[src[i] * WPR + (dst[i] >> 5)], 1u << (dst[i] & 31));
        atomicOr(&g_bits[dst[i] * WPR + (src[i] >> 5)], 1u << (src[i] & 31));
    }
}

// ---------------------------------------------------------------------------
// deg[i] = popcount(row i)
__global__ void deg_kernel() {
    int row = blockIdx.x * 8 + (threadIdx.x >> 5);
    if (row >= N_NODES) return;
    int lane = threadIdx.x & 31;
    const uint32_t* w = &g_bits[row * WPR];
    unsigned cnt = 0;
    for (int i = lane; i < WPR; i += 32) cnt += __popc(w[i]);
    #pragma unroll
    for (int o = 16; o; o >>= 1) cnt += __shfl_down_sync(0xffffffffu, cnt, o);
    if (lane == 0) g_deg[row] = (int)cnt;
}

// ---------------------------------------------------------------------------
// Tensor-core GEMM: h = x @ W -> fp16 (unscaled). Byte-identical to R15.
#define BM 128
#define BN 64
#define GBK 32
#define LDP (GBK + 8)
#define XBUF (BM * LDP)
#define WBUF (BN * LDP)

__device__ __forceinline__ void ldsm4(uint32_t* r, uint32_t addr) {
    asm volatile("ldmatrix.sync.aligned.m8n8.x4.shared.b16 {%0,%1,%2,%3}, [%4];"
                 : "=r"(r[0]), "=r"(r[1]), "=r"(r[2]), "=r"(r[3]) : "r"(addr));
}
__device__ __forceinline__ void mma16816(float* c, const uint32_t* a, uint32_t b0, uint32_t b1) {
    asm volatile("mma.sync.aligned.m16n8k16.row.col.f32.f16.f16.f32 "
                 "{%0,%1,%2,%3},{%4,%5,%6,%7},{%8,%9},{%0,%1,%2,%3};"
                 : "+f"(c[0]), "+f"(c[1]), "+f"(c[2]), "+f"(c[3])
                 : "r"(a[0]), "r"(a[1]), "r"(a[2]), "r"(a[3]), "r"(b0), "r"(b1));
}

__global__ __launch_bounds__(256, 2) void gemm_mma_kernel(const float* __restrict__ x) {
    __shared__ __half xs[2][BM][LDP];
    __shared__ __half ws[2][BN][LDP];
    const int t = threadIdx.x;
    const int lane = t & 31, wid = t >> 5;
    const int warpm = wid >> 1, warpn = wid & 1;
    const int m0 = blockIdx.x * BM, n0 = blockIdx.y * BN;

    const int ar = t >> 3, ac4 = (t & 7) * 4;
    const int br = t >> 2, bc = (t & 3) * 8;

    float acc[2][4][4];
    #pragma unroll
    for (int i = 0; i < 2; i++)
        #pragma unroll
        for (int j = 0; j < 4; j++)
            #pragma unroll
            for (int q = 0; q < 4; q++) acc[i][j][q] = 0.0f;

    const uint32_t xs_u = (uint32_t)__cvta_generic_to_shared(&xs[0][0][0]);
    const uint32_t ws_u = (uint32_t)__cvta_generic_to_shared(&ws[0][0][0]);
    const int lr = lane & 7, sel = lane >> 3;
    const int a_row = warpm * 32 + lr + ((sel & 1) ? 8 : 0);
    const int a_col = (sel & 2) ? 8 : 0;
    const uint32_t aA0 = xs_u + (uint32_t)(a_row * LDP + a_col) * 2u;
    const int b_row = warpn * 32 + lr + ((sel & 2) ? 8 : 0);
    const int b_col = (sel & 1) ? 8 : 0;

    {
        #pragma unroll
        for (int j = 0; j < 4; j++) {
            int row = ar + j * 32, gm = m0 + row;
            float4 v = (gm < N_NODES) ? *(const float4*)&x[gm * D + ac4]
                                      : make_float4(0.f, 0.f, 0.f, 0.f);
            __half2* dst = (__half2*)&xs[0][row][ac4];
            dst[0] = __floats2half2_rn(v.x, v.y);
            dst[1] = __floats2half2_rn(v.z, v.w);
        }
        *(uint4*)&ws[0][br][bc] = *(const uint4*)&g_wt[(n0 + br) * D + bc];
    }
    __syncthreads();

    #pragma unroll
    for (int kt = 0; kt < D / GBK; kt++) {
        const int cur = kt & 1;
        float4 pa[4];
        uint4 pb;
        if (kt < D / GBK - 1) {
            int kn = (kt + 1) * GBK;
            #pragma unroll
            for (int j = 0; j < 4; j++) {
                int gm = m0 + ar + j * 32;
                pa[j] = (gm < N_NODES) ? *(const float4*)&x[gm * D + kn + ac4]
                                       : make_float4(0.f, 0.f, 0.f, 0.f);
            }
            pb = *(const uint4*)&g_wt[(n0 + br) * D + kn + bc];
        }
        const uint32_t aA = aA0 + cur * (uint32_t)(XBUF * 2);
        const uint32_t wsbase = ws_u + cur * (uint32_t)(WBUF * 2);
        const uint32_t aBc = wsbase + (uint32_t)(b_row * LDP + b_col) * 2u;
        #pragma unroll
        for (int s = 0; s < GBK / 16; s++) {
            uint32_t A0[4], A1[4], B0[4], B1[4];
            ldsm4(A0, aA + s * 32u);
            ldsm4(A1, aA + 16u * LDP * 2u + s * 32u);
            ldsm4(B0, aBc + s * 32u);
            ldsm4(B1, aBc + 16u * LDP * 2u + s * 32u);
            mma16816(acc[0][0], A0, B0[0], B0[1]);
            mma16816(acc[0][1], A0, B0[2], B0[3]);
            mma16816(acc[0][2], A0, B1[0], B1[1]);
            mma16816(acc[0][3], A0, B1[2], B1[3]);
            mma16816(acc[1][0], A1, B0[0], B0[1]);
            mma16816(acc[1][1], A1, B0[2], B0[3]);
            mma16816(acc[1][2], A1, B1[0], B1[1]);
            mma16816(acc[1][3], A1, B1[2], B1[3]);
        }
        if (kt < D / GBK - 1) {
            const int nxt = cur ^ 1;
            #pragma unroll
            for (int j = 0; j < 4; j++) {
                __half2* dst = (__half2*)&xs[nxt][ar + j * 32][ac4];
                dst[0] = __floats2half2_rn(pa[j].x, pa[j].y);
                dst[1] = __floats2half2_rn(pa[j].z, pa[j].w);
            }
            *(uint4*)&ws[nxt][br][bc] = pb;
            __syncthreads();
        }
    }

    const int r_base = m0 + warpm * 32 + (lane >> 2);
    const int c_base = n0 + warpn * 32 + (lane & 3) * 2;
    #pragma unroll
    for (int mt = 0; mt < 2; mt++) {
        int gr0 = r_base + mt * 16;
        int gr1 = gr0 + 8;
        #pragma unroll
        for (int nt = 0; nt < 4; nt++) {
            int gc = c_base + nt * 8;
            if (gr0 < N_NODES)
                g_hh[gr0 * (D / 2) + (gc >> 1)] = __floats2half2_rn(acc[mt][nt][0], acc[mt][nt][1]);
            if (gr1 < N_NODES)
                g_hh[gr1 * (D / 2) + (gc >> 1)] = __floats2half2_rn(acc[mt][nt][2], acc[mt][nt][3]);
        }
    }
}

// ---------------------------------------------------------------------------
// out[i,:] = dinv[i] * ( sum_{j in N(i)} dinv[j]*h[j,:] + dinv[i]*h[i,:] )
// h stored UNSCALED; dinv[j] applied in-gather via HMUL2. Extraction packs
// {uint4 row offset, dinv[j] as half2} into one int2 -> single LDS.64/neighbor.
__global__ __launch_bounds__(128) void agg_kernel(float* __restrict__ out) {
    __shared__ int2 s_pair[MAXDEG];
    __shared__ int s_wsum[4];
    __shared__ float2 s_red[4][32][4];   // [warp][lane][comp] = 4KB
    const int row = blockIdx.x;
    const int t = threadIdx.x;
    const int lane = t & 31, wid = t >> 5;
    const uint32_t* __restrict__ wr = &g_bits[row * WPR];

    uint32_t w[3];
    int cnt = 0;
    const int wbase = t * 3;
    #pragma unroll
    for (int i = 0; i < 3; i++) {
        int wi = wbase + i;
        w[i] = (wi < WPR) ? wr[wi] : 0u;
        cnt += __popc(w[i]);
    }
    int inc = cnt;
    #pragma unroll
    for (int o = 1; o < 32; o <<= 1) {
        int v = __shfl_up_sync(0xffffffffu, inc, o);
        if (lane >= o) inc += v;
    }
    if (lane == 31) s_wsum[wid] = inc;
    __syncthreads();
    int base = 0, tot = 0;
    #pragma unroll
    for (int i = 0; i < 4; i++) {
        int v = s_wsum[i];
        if (i < wid) base += v;
        tot += v;
    }
    int pos = base + inc - cnt;
    #pragma unroll
    for (int i = 0; i < 3; i++) {
        uint32_t ww = w[i];
        int b32 = (wbase + i) * 32;
        while (ww) {
            int b = __ffs(ww) - 1;
            ww &= ww - 1;
            int j = b32 + b;
            __half2 dj2 = __float2half2_rn(rsqrtf((float)g_deg[j] + 1.0f));
            s_pair[pos++] = make_int2(j * (D / 8), *(int*)&dj2);
        }
    }
    __syncthreads();

    const uint4* __restrict__ hh4 = (const uint4*)g_hh;
    float2 acc[4];
    #pragma unroll
    for (int c = 0; c < 4; c++) acc[c] = make_float2(0.f, 0.f);

    int k = wid;
    for (; k + 12 < tot; k += 16) {
        int2 p0 = s_pair[k], p1 = s_pair[k + 4], p2 = s_pair[k + 8], p3 = s_pair[k + 12];
        uint4 u0 = hh4[p0.x + lane];
        uint4 u1 = hh4[p1.x + lane];
        uint4 u2 = hh4[p2.x + lane];
        uint4 u3 = hh4[p3.x + lane];
        __half2 d0 = *(__half2*)&p0.y, d1 = *(__half2*)&p1.y;
        __half2 d2 = *(__half2*)&p2.y, d3 = *(__half2*)&p3.y;
        const __half2* a = (const __half2*)&u0;
        const __half2* b = (const __half2*)&u1;
        const __half2* c2 = (const __half2*)&u2;
        const __half2* d = (const __half2*)&u3;
        #pragma unroll
        for (int c = 0; c < 4; c++) {
            __half2 s = __hadd2(__hadd2(__hmul2(a[c], d0), __hmul2(b[c], d1)),
                                __hadd2(__hmul2(c2[c], d2), __hmul2(d[c], d3)));
            float2 f = __half22float2(s);
            acc[c].x += f.x;
            acc[c].y += f.y;
        }
    }
    for (; k < tot; k += 4) {
        int2 p = s_pair[k];
        uint4 u = hh4[p.x + lane];
        __half2 dj = *(__half2*)&p.y;
        const __half2* a = (const __half2*)&u;
        #pragma unroll
        for (int c = 0; c < 4; c++) {
            float2 f = __half22float2(__hmul2(a[c], dj));
            acc[c].x += f.x;
            acc[c].y += f.y;
        }
    }
    #pragma unroll
    for (int c = 0; c < 4; c++) s_red[wid][lane][c] = acc[c];
    __syncthreads();

    {
        int rl = t >> 2, rc = t & 3;
        float2 v0 = s_red[0][rl][rc], v1 = s_red[1][rl][rc];
        float2 v2 = s_red[2][rl][rc], v3 = s_red[3][rl][rc];
        float2 v;
        v.x = (v0.x + v1.x) + (v2.x + v3.x);
        v.y = (v0.y + v1.y) + (v2.y + v3.y);
        float di = rsqrtf((float)tot + 1.0f);   // tot == deg[row]
        float2 self = __half22float2(g_hh[row * (D / 2) + t]);   // UNSCALED
        float2 o;
        o.x = di * (v.x + di * self.x);
        o.y = di * (v.y + di * self.y);
        ((float2*)out)[row * (D / 2) + t] = o;
    }
}

// ---------------------------------------------------------------------------
// Fork-join (capture-correct, proven):
//   stream0: evRoot ─ detect ─ evD ── gemm ─────── wait(evB) ─ agg
//   s2:      wait(evRoot) ─ clear ─ wait(evD) ─ set_bits ─ deg ─ evB
extern "C" void kernel_launch(void* const* d_in, const int* in_sizes, int n_in,
                              void* d_out, int out_size) {
    const float* x  = (const float*)d_in[0];
    const int*   ei = (const int*)d_in[1];
    const float* w  = (const float*)d_in[2];
    float* out = (float*)d_out;

    cudaStream_t s2;
    cudaEvent_t evRoot, evD, evB;
    cudaStreamCreateWithFlags(&s2, cudaStreamNonBlocking);
    cudaEventCreateWithFlags(&evRoot, cudaEventDisableTiming);
    cudaEventCreateWithFlags(&evD, cudaEventDisableTiming);
    cudaEventCreateWithFlags(&evB, cudaEventDisableTiming);

    cudaEventRecord(evRoot, 0);
    cudaStreamWaitEvent(s2, evRoot, 0);
    clear_kernel<<<(N_NODES * WPR / 4 + 255) / 256, 256, 0, s2>>>();   // #1

    detect_kernel<<<256, 256>>>(ei, w);                                // #2
    cudaEventRecord(evD, 0);
    cudaStreamWaitEvent(s2, evD, 0);

    gemm_mma_kernel<<<dim3((N_NODES + BM - 1) / BM, D / BN), 256>>>(x);  // #3 (∥ chain B)
    set_bits_kernel<<<(E_EDGES / 4 + 255) / 256, 256, 0, s2>>>(ei);      // #4
    deg_kernel<<<(N_NODES + 7) / 8, 256, 0, s2>>>();                     // #5
    cudaEventRecord(evB, s2);
    cudaStreamWaitEvent(0, evB, 0);                                      // join

    agg_kernel<<<N_NODES, 128>>>(out);                                   // #6 -> profiled
}